// round 10
// baseline (speedup 1.0000x reference)
#include <cuda_runtime.h>
#include <math.h>
#include <stdint.h>

// ---------------------------------------------------------------------------
// Problem constants: N=32768 tokens, C=512, H=8, D=64; 64 windows x 512 tokens
// ---------------------------------------------------------------------------

// Scratch (static device arrays; no allocations anywhere)
__device__ float g_q[64 * 8 * 512 * 64];   // [w][h][m][d]
__device__ float g_k[64 * 8 * 512 * 64];
__device__ float g_v[64 * 8 * 512 * 64];
__device__ float g_h[32768 * 512];         // [n][h*64+d] (inverse-permuted)
__device__ float g_wqkvT[1536 * 512];      // wqkv transposed: [j][k]
__device__ float g_woutT[512 * 512];       // wout  transposed: [j][k]

// ---------------------------------------------------------------------------
// Helpers
// ---------------------------------------------------------------------------
__device__ __forceinline__ uint32_t cvt_tf32(float f) {
    uint32_t u; asm("cvt.rna.tf32.f32 %0, %1;" : "=r"(u) : "f"(f)); return u;
}

__device__ __forceinline__ void mma_tf32(float c[4], uint32_t a0, uint32_t a1,
                                         uint32_t a2, uint32_t a3,
                                         uint32_t b0, uint32_t b1) {
    asm volatile(
        "mma.sync.aligned.m16n8k8.row.col.f32.tf32.tf32.f32 "
        "{%0,%1,%2,%3}, {%4,%5,%6,%7}, {%8,%9}, {%0,%1,%2,%3};"
        : "+f"(c[0]), "+f"(c[1]), "+f"(c[2]), "+f"(c[3])
        : "r"(a0), "r"(a1), "r"(a2), "r"(a3), "r"(b0), "r"(b1));
}

// ---------------------------------------------------------------------------
// K0: 2D transpose dst[C][R] = src[R][C]
// ---------------------------------------------------------------------------
__global__ void transpose_k(const float* __restrict__ src,
                            float* __restrict__ dst, int R, int C)
{
    __shared__ float t[32][33];
    int bx = blockIdx.x << 5, by = blockIdx.y << 5;
    int x = threadIdx.x, y = threadIdx.y;   // 32 x 8
#pragma unroll
    for (int i = 0; i < 32; i += 8)
        t[y + i][x] = src[(size_t)(by + y + i) * C + bx + x];
    __syncthreads();
#pragma unroll
    for (int i = 0; i < 32; i += 8)
        dst[(size_t)(bx + y + i) * R + by + x] = t[x][y + i];
}

// ---------------------------------------------------------------------------
// tf32 mma.sync GEMM: C[128,128] tile, K=512, 2 CTAs/SM.
// K-chunk 64 (was 32): single-buffered fragment smem, 2 barriers per chunk,
// 8 chunks -> 15 barriers/CTA (was 32) and 16 LDG.128/thread per stage
// (doubled MLP).  Fragment staging algebra lifted verbatim from the
// validated attention-kernel Q/K staging (straight lane<<2 consumer).
// ---------------------------------------------------------------------------
#define GEMM_DYN_SMEM ((8192 + 8192) * 4)   // sA + sB = 64 KB

__global__ __launch_bounds__(256, 2)
void gemm_mma(const float* __restrict__ A, const float* __restrict__ BT,
              const float* __restrict__ bias, const int* __restrict__ coords,
              const float* __restrict__ gq, const float* __restrict__ gk,
              float* __restrict__ outp, int mode)
{
    extern __shared__ float dyn[];
    float* sA = dyn;            // 8192 floats: 64 frag tiles (mt*8 + tk)
    float* sB = dyn + 8192;     // 8192 floats: 64 frag tiles (tk*8 + nt)
    __shared__ float sBias[128];
    __shared__ float sGam[128];
    __shared__ float sRed[128][4];

    const int tid = threadIdx.x;
    const int lane = tid & 31, wid = tid >> 5;
    const int wm = wid & 1, wn = wid >> 1;
    const int gid = lane >> 2, tig = lane & 3;
    const int m0 = blockIdx.y << 7;
    const int j0 = blockIdx.x << 7;
    const int sec = j0 >> 9;

    if (tid < 128) {
        sBias[tid] = bias[j0 + tid];
        float g = 1.0f;
        if (mode == 0) {
            if (sec == 0) g = gq[(j0 & 511) + tid];
            else if (sec == 1) g = gk[(j0 & 511) + tid];
        }
        sGam[tid] = g;
    }

    float c[4][4][4];
#pragma unroll
    for (int mi = 0; mi < 4; mi++)
#pragma unroll
        for (int ni = 0; ni < 4; ni++)
#pragma unroll
            for (int q = 0; q < 4; q++) c[mi][ni][q] = 0.f;

    for (int s = 0; s < 8; s++) {
        const int kb = s << 6;
        if (s) __syncthreads();
        // ---- stage A (A-frag layout; == attention sQ staging) ----
#pragma unroll
        for (int p = 0; p < 8; p++) {
            int idx = (p << 8) + tid;       // float4 unit 0..2047
            int r = idx >> 4, dq = idx & 15;
            float4 v = *(const float4*)&A[(size_t)(m0 + r) * 512 + kb + (dq << 2)];
            int base = ((((r >> 4) << 3) + (dq >> 1)) << 7) + ((r & 7) << 4)
                     + ((r >> 3) & 1) + ((dq & 1) << 1);
            sA[base + 0]  = __uint_as_float(cvt_tf32(v.x));
            sA[base + 4]  = __uint_as_float(cvt_tf32(v.y));
            sA[base + 8]  = __uint_as_float(cvt_tf32(v.z));
            sA[base + 12] = __uint_as_float(cvt_tf32(v.w));
        }
        // ---- stage B (B-frag layout; == attention sK staging, 8 n-tiles) ----
#pragma unroll
        for (int p = 0; p < 8; p++) {
            int idx = (p << 8) + tid;
            int n = idx >> 4, dq = idx & 15;
            float4 v = *(const float4*)&BT[(size_t)(j0 + n) * 512 + kb + (dq << 2)];
            int base = ((((dq >> 1) << 3) + (n >> 4)) << 7) + ((n & 7) << 4)
                     + (dq & 1) + (((n >> 3) & 1) << 1);
            sB[base + 0]  = __uint_as_float(cvt_tf32(v.x));
            sB[base + 4]  = __uint_as_float(cvt_tf32(v.y));
            sB[base + 8]  = __uint_as_float(cvt_tf32(v.z));
            sB[base + 12] = __uint_as_float(cvt_tf32(v.w));
        }
        __syncthreads();
        // ---- consume: 8 k8 steps ----
#pragma unroll
        for (int tk = 0; tk < 8; tk++) {
            const int lx = lane << 2;
            uint4 a[4];
#pragma unroll
            for (int mi = 0; mi < 4; mi++)
                a[mi] = *(const uint4*)&sA[(((((wm << 2) + mi) << 3) + tk) << 7) + lx];
            uint4 b[2];
#pragma unroll
            for (int pi = 0; pi < 2; pi++)
                b[pi] = *(const uint4*)&sB[(((tk << 3) + (wn << 1) + pi) << 7) + lx];
#pragma unroll
            for (int mi = 0; mi < 4; mi++)
#pragma unroll
                for (int pi = 0; pi < 2; pi++) {
                    mma_tf32(c[mi][pi * 2],     a[mi].x, a[mi].y, a[mi].z, a[mi].w,
                             b[pi].x, b[pi].y);
                    mma_tf32(c[mi][pi * 2 + 1], a[mi].x, a[mi].y, a[mi].z, a[mi].w,
                             b[pi].z, b[pi].w);
                }
        }
    }

    if (mode == 1) {
#pragma unroll
        for (int mi = 0; mi < 4; mi++)
#pragma unroll
            for (int ni = 0; ni < 4; ni++) {
                int col = (wn << 5) + (ni << 3) + (tig << 1);
                int rlo = m0 + (wm << 6) + (mi << 4) + gid;
                float2 v0 = make_float2(c[mi][ni][0] + sBias[col],
                                        c[mi][ni][1] + sBias[col + 1]);
                float2 v1 = make_float2(c[mi][ni][2] + sBias[col],
                                        c[mi][ni][3] + sBias[col + 1]);
                *(float2*)&outp[(size_t)rlo * 512 + j0 + col] = v0;
                *(float2*)&outp[(size_t)(rlo + 8) * 512 + j0 + col] = v1;
            }
        return;
    }

#pragma unroll
    for (int mi = 0; mi < 4; mi++)
#pragma unroll
        for (int ni = 0; ni < 4; ni++) {
            int col = (wn << 5) + (ni << 3) + (tig << 1);
            c[mi][ni][0] += sBias[col];
            c[mi][ni][1] += sBias[col + 1];
            c[mi][ni][2] += sBias[col];
            c[mi][ni][3] += sBias[col + 1];
        }

    if (sec < 2) {
#pragma unroll
        for (int mi = 0; mi < 4; mi++)
#pragma unroll
            for (int h = 0; h < 2; h++) {
                float ss = 0.f;
#pragma unroll
                for (int ni = 0; ni < 4; ni++) {
                    float x0 = c[mi][ni][2 * h], x1 = c[mi][ni][2 * h + 1];
                    ss += x0 * x0 + x1 * x1;
                }
                ss += __shfl_xor_sync(0xffffffffu, ss, 1);
                ss += __shfl_xor_sync(0xffffffffu, ss, 2);
                if (tig == 0)
                    sRed[(wm << 6) + (mi << 4) + gid + (h << 3)][wn] = ss;
            }
        __syncthreads();
#pragma unroll
        for (int mi = 0; mi < 4; mi++)
#pragma unroll
            for (int h = 0; h < 2; h++) {
                int rl = (wm << 6) + (mi << 4) + gid + (h << 3);
                float tot = sRed[rl][wn] + sRed[rl][wn ^ 1];
                float inv = 8.0f / fmaxf(sqrtf(tot), 1e-12f);
#pragma unroll
                for (int ni = 0; ni < 4; ni++) {
                    int col = (wn << 5) + (ni << 3) + (tig << 1);
                    c[mi][ni][2 * h]     *= inv * sGam[col];
                    c[mi][ni][2 * h + 1] *= inv * sGam[col + 1];
                }
            }
    }

    float* dst = (sec == 0) ? g_q : ((sec == 1) ? g_k : g_v);
    const int head = ((j0 & 511) >> 6) + (wn >> 1);
    const int dbase = ((wn & 1) << 5) + (tig << 1);
#pragma unroll
    for (int mi = 0; mi < 4; mi++)
#pragma unroll
        for (int h = 0; h < 2; h++) {
            int token = m0 + (wm << 6) + (mi << 4) + gid + (h << 3);
            int cx = coords[4 * token + 1];
            int cy = coords[4 * token + 2];
            int cz = coords[4 * token + 3];
            int w = ((cx >> 3) << 4) + ((cy >> 3) << 2) + (cz >> 3);
            int m = ((cz & 7) << 6) + ((cy & 7) << 3) + (cx & 7);
            size_t bb = ((size_t)((w << 3) + head) * 512 + m) * 64 + dbase;
#pragma unroll
            for (int ni = 0; ni < 4; ni++)
                *(float2*)&dst[bb + (ni << 3)] =
                    make_float2(c[mi][ni][2 * h], c[mi][ni][2 * h + 1]);
        }
}

// ---------------------------------------------------------------------------
// K2: window attention via tf32 mma.sync — 32-row warp tiles + triple-buffered
// K/V fragment smem, one barrier per chunk (R8-validated, unchanged).
// ---------------------------------------------------------------------------
#define ATTN_SMEM_BYTES ((8192 * 2 + 3 * 4096 + 3 * 4096) * 4)

__global__ __launch_bounds__(256, 1)
void window_attn_mma()
{
    extern __shared__ float sm[];
    float* sQ = sm;              // 16384 floats: 128 frag tiles (mt*8 + tkd)
    float* sK = sm + 16384;      // 3 x 4096 floats
    float* sV = sm + 16384 + 3 * 4096;   // 3 x 4096 floats

    const int tid = threadIdx.x;
    const int lane = tid & 31, wid = tid >> 5;
    const int gid = lane >> 2, tig = lane & 3;
    const int qt = blockIdx.x;          // 0..1
    const int wh = blockIdx.y;          // w*8 + h
    const int m0 = qt << 8;             // 256 rows per CTA

    const float* qbase = g_q + ((size_t)wh * 512 + m0) * 64;
    const float* kbase = g_k + (size_t)wh * 512 * 64;
    const float* vbase = g_v + (size_t)wh * 512 * 64;

    auto stage = [&](int c, int bi) {
        float* sKc = sK + bi * 4096;
        float* sVc = sV + bi * 4096;
#pragma unroll
        for (int p = 0; p < 4; p++) {
            int idx = (p << 8) + tid;       // float4 unit 0..1023
            int key = idx >> 4, dq = idx & 15;
            float4 v = *(const float4*)&kbase[(size_t)((c << 6) + key) * 64 + (dq << 2)];
            int base = ((((dq >> 1) << 2) + (key >> 4)) << 7) + ((key & 7) << 4)
                     + (dq & 1) + (((key >> 3) & 1) << 1);
            sKc[base + 0]  = __uint_as_float(cvt_tf32(v.x));
            sKc[base + 4]  = __uint_as_float(cvt_tf32(v.y));
            sKc[base + 8]  = __uint_as_float(cvt_tf32(v.z));
            sKc[base + 12] = __uint_as_float(cvt_tf32(v.w));
        }
#pragma unroll
        for (int p = 0; p < 4; p++) {
            int idx = (p << 8) + tid;
            int key = idx >> 4, dq = idx & 15;
            float4 v = *(const float4*)&vbase[(size_t)((c << 6) + key) * 64 + (dq << 2)];
            int d0 = dq << 2;
            int base = ((((key >> 3) << 2) + (dq >> 2)) << 7)
                     + ((key >> 2) & 1) + (((dq >> 1) & 1) << 1)
                     + (((d0 & 7) << 2) + (key & 3)) * 4;
            sVc[base + 0]  = __uint_as_float(cvt_tf32(v.x));
            sVc[base + 16] = __uint_as_float(cvt_tf32(v.y));
            sVc[base + 32] = __uint_as_float(cvt_tf32(v.z));
            sVc[base + 48] = __uint_as_float(cvt_tf32(v.w));
        }
    };

    // ---- stage Q once (A-frag layout, pre-scaled by 1/sqrt(D)=0.125) ----
#pragma unroll
    for (int p = 0; p < 16; p++) {
        int idx = (p << 8) + tid;       // float4 unit 0..4095
        int r = idx >> 4, dq = idx & 15;
        float4 v = *(const float4*)&qbase[(size_t)r * 64 + (dq << 2)];
        int base = ((((r >> 4) << 3) + (dq >> 1)) << 7) + ((r & 7) << 4)
                 + ((r >> 3) & 1) + ((dq & 1) << 1);
        sQ[base + 0]  = __uint_as_float(cvt_tf32(v.x * 0.125f));
        sQ[base + 4]  = __uint_as_float(cvt_tf32(v.y * 0.125f));
        sQ[base + 8]  = __uint_as_float(cvt_tf32(v.z * 0.125f));
        sQ[base + 12] = __uint_as_float(cvt_tf32(v.w * 0.125f));
    }
    stage(0, 0);

    float cO[2][8][4];
#pragma unroll
    for (int mi = 0; mi < 2; mi++)
#pragma unroll
        for (int f = 0; f < 8; f++)
#pragma unroll
            for (int q = 0; q < 4; q++) cO[mi][f][q] = 0.f;
    float mr[2][2], lr[2][2];
#pragma unroll
    for (int mi = 0; mi < 2; mi++) {
        mr[mi][0] = -1e30f; mr[mi][1] = -1e30f;
        lr[mi][0] = 0.f;    lr[mi][1] = 0.f;
    }

    int bufc = 0;
    for (int c = 0; c < 8; c++) {
        if (c < 7) {
            int bn = bufc + 1; if (bn == 3) bn = 0;
            stage(c + 1, bn);
        }
        __syncthreads();
        const float* sKc = sK + bufc * 4096;
        const float* sVc = sV + bufc * 4096;

        // ---- S = Q K^T (pre-scaled): 2 m-tiles x 8 n-tiles ----
        float cS[2][8][4];
#pragma unroll
        for (int mi = 0; mi < 2; mi++)
#pragma unroll
            for (int f = 0; f < 8; f++)
#pragma unroll
                for (int q = 0; q < 4; q++) cS[mi][f][q] = 0.f;
#pragma unroll
        for (int tkd = 0; tkd < 8; tkd++) {
            uint4 qa[2];
#pragma unroll
            for (int mi = 0; mi < 2; mi++)
                qa[mi] = *(const uint4*)&sQ[(((((wid << 1) + mi) << 3) + tkd) << 7)
                                            + (lane << 2)];
#pragma unroll
            for (int tn2 = 0; tn2 < 4; tn2++) {
                uint4 kb = *(const uint4*)&sKc[(((tkd << 2) + tn2) << 7) + (lane << 2)];
#pragma unroll
                for (int mi = 0; mi < 2; mi++) {
                    mma_tf32(cS[mi][tn2 * 2],     qa[mi].x, qa[mi].y, qa[mi].z,
                             qa[mi].w, kb.x, kb.y);
                    mma_tf32(cS[mi][tn2 * 2 + 1], qa[mi].x, qa[mi].y, qa[mi].z,
                             qa[mi].w, kb.z, kb.w);
                }
            }
        }

        // ---- online softmax per m-tile (rows gid, gid+8) ----
#pragma unroll
        for (int mi = 0; mi < 2; mi++) {
            float smax0 = -1e30f, smax1 = -1e30f;
#pragma unroll
            for (int f = 0; f < 8; f++) {
                smax0 = fmaxf(smax0, fmaxf(cS[mi][f][0], cS[mi][f][1]));
                smax1 = fmaxf(smax1, fmaxf(cS[mi][f][2], cS[mi][f][3]));
            }
            smax0 = fmaxf(smax0, __shfl_xor_sync(0xffffffffu, smax0, 1));
            smax0 = fmaxf(smax0, __shfl_xor_sync(0xffffffffu, smax0, 2));
            smax1 = fmaxf(smax1, __shfl_xor_sync(0xffffffffu, smax1, 1));
            smax1 = fmaxf(smax1, __shfl_xor_sync(0xffffffffu, smax1, 2));
            float mn0 = fmaxf(mr[mi][0], smax0), mn1 = fmaxf(mr[mi][1], smax1);
            float corr0 = __expf(mr[mi][0] - mn0), corr1 = __expf(mr[mi][1] - mn1);
            mr[mi][0] = mn0; mr[mi][1] = mn1;
            float rs0 = 0.f, rs1 = 0.f;
#pragma unroll
            for (int f = 0; f < 8; f++) {
                float p0 = __expf(cS[mi][f][0] - mn0);
                float p1 = __expf(cS[mi][f][1] - mn0);
                float p2 = __expf(cS[mi][f][2] - mn1);
                float p3 = __expf(cS[mi][f][3] - mn1);
                rs0 += p0 + p1; rs1 += p2 + p3;
                cS[mi][f][0] = __uint_as_float(cvt_tf32(p0));
                cS[mi][f][1] = __uint_as_float(cvt_tf32(p1));
                cS[mi][f][2] = __uint_as_float(cvt_tf32(p2));
                cS[mi][f][3] = __uint_as_float(cvt_tf32(p3));
            }
            rs0 += __shfl_xor_sync(0xffffffffu, rs0, 1);
            rs0 += __shfl_xor_sync(0xffffffffu, rs0, 2);
            rs1 += __shfl_xor_sync(0xffffffffu, rs1, 1);
            rs1 += __shfl_xor_sync(0xffffffffu, rs1, 2);
            lr[mi][0] = lr[mi][0] * corr0 + rs0;
            lr[mi][1] = lr[mi][1] * corr1 + rs1;
#pragma unroll
            for (int f = 0; f < 8; f++) {
                cO[mi][f][0] *= corr0; cO[mi][f][1] *= corr0;
                cO[mi][f][2] *= corr1; cO[mi][f][3] *= corr1;
            }
        }

        // ---- O += P V : shfl P C-frag -> A-frag; V frags reused by both mi ----
        const int src  = (lane & 28) | (tig >> 1);
        const int src2 = src + 2;
        const bool odd = tig & 1;
#pragma unroll
        for (int kb = 0; kb < 8; kb++) {
            uint32_t pa[2][4];
#pragma unroll
            for (int mi = 0; mi < 2; mi++) {
                float v0 = __shfl_sync(0xffffffffu, cS[mi][kb][0], src);
                float v1 = __shfl_sync(0xffffffffu, cS[mi][kb][1], src);
                float v2 = __shfl_sync(0xffffffffu, cS[mi][kb][2], src);
                float v3 = __shfl_sync(0xffffffffu, cS[mi][kb][3], src);
                float w0 = __shfl_sync(0xffffffffu, cS[mi][kb][0], src2);
                float w1 = __shfl_sync(0xffffffffu, cS[mi][kb][1], src2);
                float w2 = __shfl_sync(0xffffffffu, cS[mi][kb][2], src2);
                float w3 = __shfl_sync(0xffffffffu, cS[mi][kb][3], src2);
                pa[mi][0] = __float_as_uint(odd ? v1 : v0);
                pa[mi][1] = __float_as_uint(odd ? v3 : v2);
                pa[mi][2] = __float_as_uint(odd ? w1 : w0);
                pa[mi][3] = __float_as_uint(odd ? w3 : w2);
            }
#pragma unroll
            for (int tn = 0; tn < 4; tn++) {
                uint4 vb = *(const uint4*)&sVc[(((kb << 2) + tn) << 7) + (lane << 2)];
#pragma unroll
                for (int mi = 0; mi < 2; mi++) {
                    mma_tf32(cO[mi][tn * 2],     pa[mi][0], pa[mi][1], pa[mi][2],
                             pa[mi][3], vb.x, vb.y);
                    mma_tf32(cO[mi][tn * 2 + 1], pa[mi][0], pa[mi][1], pa[mi][2],
                             pa[mi][3], vb.z, vb.w);
                }
            }
        }
        bufc++; if (bufc == 3) bufc = 0;
    }

    // ---- epilogue: 1/l and inverse-permutation scatter ----
    const int w = wh >> 3, h = wh & 7;
    const int wx = w >> 4, wy = (w >> 2) & 3, wz = w & 3;
#pragma unroll
    for (int mi = 0; mi < 2; mi++)
#pragma unroll
        for (int rr = 0; rr < 2; rr++) {
            int m = m0 + (wid << 5) + (mi << 4) + gid + (rr << 3);
            int mz = m >> 6, my = (m >> 3) & 7, mx = m & 7;
            int n = (wz * 8 + mz) * 1024 + (wy * 8 + my) * 32 + (wx * 8 + mx);
            float inv = 1.0f / lr[mi][rr];
            float* dsth = g_h + (size_t)n * 512 + h * 64 + (tig << 1);
#pragma unroll
            for (int f = 0; f < 8; f++)
                *(float2*)&dsth[f << 3] =
                    make_float2(cO[mi][f][2 * rr] * inv,
                                cO[mi][f][2 * rr + 1] * inv);
        }
}

// ---------------------------------------------------------------------------
// kernel_launch
// inputs: x_feats, coords, w_qkv, b_qkv, gamma_q, gamma_k, w_out, b_out
// ---------------------------------------------------------------------------
extern "C" void kernel_launch(void* const* d_in, const int* in_sizes, int n_in,
                              void* d_out, int out_size)
{
    (void)in_sizes; (void)n_in; (void)out_size;
    const float* x      = (const float*)d_in[0];
    const int*   coords = (const int*)  d_in[1];
    const float* wqkv   = (const float*)d_in[2];
    const float* bqkv   = (const float*)d_in[3];
    const float* gq     = (const float*)d_in[4];
    const float* gk     = (const float*)d_in[5];
    const float* wout   = (const float*)d_in[6];
    const float* bout   = (const float*)d_in[7];
    float* outp = (float*)d_out;

    cudaFuncSetAttribute(window_attn_mma,
                         cudaFuncAttributeMaxDynamicSharedMemorySize,
                         ATTN_SMEM_BYTES);
    cudaFuncSetAttribute(gemm_mma,
                         cudaFuncAttributeMaxDynamicSharedMemorySize,
                         GEMM_DYN_SMEM);

    float* wqkvT;  cudaGetSymbolAddress((void**)&wqkvT, g_wqkvT);
    float* woutT;  cudaGetSymbolAddress((void**)&woutT, g_woutT);
    float* hbuf;   cudaGetSymbolAddress((void**)&hbuf,  g_h);

    transpose_k<<<dim3(48, 16), dim3(32, 8)>>>(wqkv, wqkvT, 512, 1536);
    transpose_k<<<dim3(16, 16), dim3(32, 8)>>>(wout, woutT, 512, 512);
    gemm_mma<<<dim3(12, 256), 256, GEMM_DYN_SMEM>>>(
        x, wqkvT, bqkv, coords, gq, gk, nullptr, 0);
    window_attn_mma<<<dim3(2, 512), 256, ATTN_SMEM_BYTES>>>();
    gemm_mma<<<dim3(4, 256), 256, GEMM_DYN_SMEM>>>(
        hbuf, woutT, bout, nullptr, nullptr, nullptr, outp, 1);
}

// round 11
// speedup vs baseline: 2.0947x; 2.0947x over previous
#include <cuda_runtime.h>
#include <math.h>
#include <stdint.h>

// ---------------------------------------------------------------------------
// Problem constants: N=32768 tokens, C=512, H=8, D=64; 64 windows x 512 tokens
// ---------------------------------------------------------------------------

// Scratch (static device arrays; no allocations anywhere)
__device__ float g_q[64 * 8 * 512 * 64];   // [w][h][m][d]
__device__ float g_k[64 * 8 * 512 * 64];
__device__ float g_v[64 * 8 * 512 * 64];
__device__ float g_h[32768 * 512];         // [n][h*64+d] (inverse-permuted)
__device__ float g_wqkvT[1536 * 512];      // wqkv transposed: [j][k]
__device__ float g_woutT[512 * 512];       // wout  transposed: [j][k]

// ---------------------------------------------------------------------------
// Helpers
// ---------------------------------------------------------------------------
__device__ __forceinline__ uint32_t cvt_tf32(float f) {
    uint32_t u; asm("cvt.rna.tf32.f32 %0, %1;" : "=r"(u) : "f"(f)); return u;
}

__device__ __forceinline__ void mma_tf32(float c[4], uint32_t a0, uint32_t a1,
                                         uint32_t a2, uint32_t a3,
                                         uint32_t b0, uint32_t b1) {
    asm volatile(
        "mma.sync.aligned.m16n8k8.row.col.f32.tf32.tf32.f32 "
        "{%0,%1,%2,%3}, {%4,%5,%6,%7}, {%8,%9}, {%0,%1,%2,%3};"
        : "+f"(c[0]), "+f"(c[1]), "+f"(c[2]), "+f"(c[3])
        : "r"(a0), "r"(a1), "r"(a2), "r"(a3), "r"(b0), "r"(b1));
}

// ---------------------------------------------------------------------------
// K0: merged 2D transposes — z=0: wqkv (512x1536), z=1: wout (512x512).
// dst[C][R] = src[R][C].  One launch instead of two.
// ---------------------------------------------------------------------------
__global__ void transpose_both(const float* __restrict__ srcA,
                               float* __restrict__ dstA,
                               const float* __restrict__ srcB,
                               float* __restrict__ dstB)
{
    __shared__ float t[32][33];
    const int z = blockIdx.z;
    const int C = z ? 512 : 1536;          // R = 512 for both
    if (z && blockIdx.x >= 16) return;     // wout needs only 16 x-tiles
    const float* src = z ? srcB : srcA;
    float* dst = z ? dstB : dstA;
    int bx = blockIdx.x << 5, by = blockIdx.y << 5;
    int x = threadIdx.x, y = threadIdx.y;   // 32 x 8
#pragma unroll
    for (int i = 0; i < 32; i += 8)
        t[y + i][x] = src[(size_t)(by + y + i) * C + bx + x];
    __syncthreads();
#pragma unroll
    for (int i = 0; i < 32; i += 8)
        dst[(size_t)(bx + y + i) * 512 + by + x] = t[x][y + i];
}

// ---------------------------------------------------------------------------
// tf32 mma.sync GEMM (R6-validated local optimum): C[128,128] tile, K=512,
// chunk 32, static smem, 2 CTAs/SM.  Do NOT add register-live state (R7/R10)
// or in-CTA pipelining (R9) — all three regressed.
// ---------------------------------------------------------------------------
__global__ __launch_bounds__(256, 2)
void gemm_mma(const float* __restrict__ A, const float* __restrict__ BT,
              const float* __restrict__ bias, const int* __restrict__ coords,
              const float* __restrict__ gq, const float* __restrict__ gk,
              float* __restrict__ outp, int mode)
{
    __shared__ float sA[4096];
    __shared__ float sB[4096];
    __shared__ float sBias[128];
    __shared__ float sGam[128];
    __shared__ float sRed[128][4];

    const int tid = threadIdx.x;
    const int lane = tid & 31, wid = tid >> 5;
    const int wm = wid & 1, wn = wid >> 1;
    const int gid = lane >> 2, tig = lane & 3;
    const int m0 = blockIdx.y << 7;
    const int j0 = blockIdx.x << 7;
    const int sec = j0 >> 9;

    if (tid < 128) {
        sBias[tid] = bias[j0 + tid];
        float g = 1.0f;
        if (mode == 0) {
            if (sec == 0) g = gq[(j0 & 511) + tid];
            else if (sec == 1) g = gk[(j0 & 511) + tid];
        }
        sGam[tid] = g;
    }

    float c[4][4][4];
#pragma unroll
    for (int mi = 0; mi < 4; mi++)
#pragma unroll
        for (int ni = 0; ni < 4; ni++)
#pragma unroll
            for (int q = 0; q < 4; q++) c[mi][ni][q] = 0.f;

    for (int s = 0; s < 16; s++) {
        const int kb = s << 5;
        if (s) __syncthreads();
#pragma unroll
        for (int p = 0; p < 4; p++) {
            int idx = (p << 8) + tid;
            int r = idx >> 3, cq = idx & 7;
            int tk = cq >> 1;
            float4 v = *(const float4*)&A[(size_t)(m0 + r) * 512 + kb + (cq << 2)];
            int base = ((((r >> 4) << 2) + tk) << 7) + ((r & 7) << 4)
                     + ((r >> 3) & 1) + ((cq & 1) << 1);
            sA[base + ((0 ^ tk) << 2)] = __uint_as_float(cvt_tf32(v.x));
            sA[base + ((1 ^ tk) << 2)] = __uint_as_float(cvt_tf32(v.y));
            sA[base + ((2 ^ tk) << 2)] = __uint_as_float(cvt_tf32(v.z));
            sA[base + ((3 ^ tk) << 2)] = __uint_as_float(cvt_tf32(v.w));
        }
#pragma unroll
        for (int p = 0; p < 4; p++) {
            int idx = (p << 8) + tid;
            int n = idx >> 3, kq = idx & 7;
            int tk = kq >> 1;
            float4 v = *(const float4*)&BT[(size_t)(j0 + n) * 512 + kb + (kq << 2)];
            int base = ((((n >> 4) << 2) + tk) << 7) + ((n & 7) << 4)
                     + ((kq & 1)) + (((n >> 3) & 1) << 1);
            sB[base + ((0 ^ tk) << 2)] = __uint_as_float(cvt_tf32(v.x));
            sB[base + ((1 ^ tk) << 2)] = __uint_as_float(cvt_tf32(v.y));
            sB[base + ((2 ^ tk) << 2)] = __uint_as_float(cvt_tf32(v.z));
            sB[base + ((3 ^ tk) << 2)] = __uint_as_float(cvt_tf32(v.w));
        }
        __syncthreads();
#pragma unroll
        for (int tk = 0; tk < 4; tk++) {
            const int lx = ((lane ^ tk) << 2);
            uint4 a[4];
#pragma unroll
            for (int mi = 0; mi < 4; mi++)
                a[mi] = *(const uint4*)&sA[(((((wm << 2) + mi) << 2) + tk) << 7) + lx];
            uint4 b[2];
#pragma unroll
            for (int pi = 0; pi < 2; pi++)
                b[pi] = *(const uint4*)&sB[(((((wn << 1) + pi) << 2) + tk) << 7) + lx];
#pragma unroll
            for (int mi = 0; mi < 4; mi++)
#pragma unroll
                for (int pi = 0; pi < 2; pi++) {
                    mma_tf32(c[mi][pi * 2],     a[mi].x, a[mi].y, a[mi].z, a[mi].w,
                             b[pi].x, b[pi].y);
                    mma_tf32(c[mi][pi * 2 + 1], a[mi].x, a[mi].y, a[mi].z, a[mi].w,
                             b[pi].z, b[pi].w);
                }
        }
    }

    if (mode == 1) {
#pragma unroll
        for (int mi = 0; mi < 4; mi++)
#pragma unroll
            for (int ni = 0; ni < 4; ni++) {
                int col = (wn << 5) + (ni << 3) + (tig << 1);
                int rlo = m0 + (wm << 6) + (mi << 4) + gid;
                float2 v0 = make_float2(c[mi][ni][0] + sBias[col],
                                        c[mi][ni][1] + sBias[col + 1]);
                float2 v1 = make_float2(c[mi][ni][2] + sBias[col],
                                        c[mi][ni][3] + sBias[col + 1]);
                *(float2*)&outp[(size_t)rlo * 512 + j0 + col] = v0;
                *(float2*)&outp[(size_t)(rlo + 8) * 512 + j0 + col] = v1;
            }
        return;
    }

#pragma unroll
    for (int mi = 0; mi < 4; mi++)
#pragma unroll
        for (int ni = 0; ni < 4; ni++) {
            int col = (wn << 5) + (ni << 3) + (tig << 1);
            c[mi][ni][0] += sBias[col];
            c[mi][ni][1] += sBias[col + 1];
            c[mi][ni][2] += sBias[col];
            c[mi][ni][3] += sBias[col + 1];
        }

    if (sec < 2) {
#pragma unroll
        for (int mi = 0; mi < 4; mi++)
#pragma unroll
            for (int h = 0; h < 2; h++) {
                float ss = 0.f;
#pragma unroll
                for (int ni = 0; ni < 4; ni++) {
                    float x0 = c[mi][ni][2 * h], x1 = c[mi][ni][2 * h + 1];
                    ss += x0 * x0 + x1 * x1;
                }
                ss += __shfl_xor_sync(0xffffffffu, ss, 1);
                ss += __shfl_xor_sync(0xffffffffu, ss, 2);
                if (tig == 0)
                    sRed[(wm << 6) + (mi << 4) + gid + (h << 3)][wn] = ss;
            }
        __syncthreads();
#pragma unroll
        for (int mi = 0; mi < 4; mi++)
#pragma unroll
            for (int h = 0; h < 2; h++) {
                int rl = (wm << 6) + (mi << 4) + gid + (h << 3);
                float tot = sRed[rl][wn] + sRed[rl][wn ^ 1];
                float inv = 8.0f / fmaxf(sqrtf(tot), 1e-12f);
#pragma unroll
                for (int ni = 0; ni < 4; ni++) {
                    int col = (wn << 5) + (ni << 3) + (tig << 1);
                    c[mi][ni][2 * h]     *= inv * sGam[col];
                    c[mi][ni][2 * h + 1] *= inv * sGam[col + 1];
                }
            }
    }

    float* dst = (sec == 0) ? g_q : ((sec == 1) ? g_k : g_v);
    const int head = ((j0 & 511) >> 6) + (wn >> 1);
    const int dbase = ((wn & 1) << 5) + (tig << 1);
#pragma unroll
    for (int mi = 0; mi < 4; mi++)
#pragma unroll
        for (int h = 0; h < 2; h++) {
            int token = m0 + (wm << 6) + (mi << 4) + gid + (h << 3);
            int cx = coords[4 * token + 1];
            int cy = coords[4 * token + 2];
            int cz = coords[4 * token + 3];
            int w = ((cx >> 3) << 4) + ((cy >> 3) << 2) + (cz >> 3);
            int m = ((cz & 7) << 6) + ((cy & 7) << 3) + (cx & 7);
            size_t bb = ((size_t)((w << 3) + head) * 512 + m) * 64 + dbase;
#pragma unroll
            for (int ni = 0; ni < 4; ni++)
                *(float2*)&dst[bb + (ni << 3)] =
                    make_float2(c[mi][ni][2 * h], c[mi][ni][2 * h + 1]);
        }
}

// ---------------------------------------------------------------------------
// K2: window attention via tf32 mma.sync — 32-row warp tiles + triple-buffered
// K/V fragment smem, one barrier per chunk (R8-validated, unchanged).
// ---------------------------------------------------------------------------
#define ATTN_SMEM_BYTES ((8192 * 2 + 3 * 4096 + 3 * 4096) * 4)

__global__ __launch_bounds__(256, 1)
void window_attn_mma()
{
    extern __shared__ float sm[];
    float* sQ = sm;              // 16384 floats: 128 frag tiles (mt*8 + tkd)
    float* sK = sm + 16384;      // 3 x 4096 floats
    float* sV = sm + 16384 + 3 * 4096;   // 3 x 4096 floats

    const int tid = threadIdx.x;
    const int lane = tid & 31, wid = tid >> 5;
    const int gid = lane >> 2, tig = lane & 3;
    const int qt = blockIdx.x;          // 0..1
    const int wh = blockIdx.y;          // w*8 + h
    const int m0 = qt << 8;             // 256 rows per CTA

    const float* qbase = g_q + ((size_t)wh * 512 + m0) * 64;
    const float* kbase = g_k + (size_t)wh * 512 * 64;
    const float* vbase = g_v + (size_t)wh * 512 * 64;

    auto stage = [&](int c, int bi) {
        float* sKc = sK + bi * 4096;
        float* sVc = sV + bi * 4096;
#pragma unroll
        for (int p = 0; p < 4; p++) {
            int idx = (p << 8) + tid;       // float4 unit 0..1023
            int key = idx >> 4, dq = idx & 15;
            float4 v = *(const float4*)&kbase[(size_t)((c << 6) + key) * 64 + (dq << 2)];
            int base = ((((dq >> 1) << 2) + (key >> 4)) << 7) + ((key & 7) << 4)
                     + (dq & 1) + (((key >> 3) & 1) << 1);
            sKc[base + 0]  = __uint_as_float(cvt_tf32(v.x));
            sKc[base + 4]  = __uint_as_float(cvt_tf32(v.y));
            sKc[base + 8]  = __uint_as_float(cvt_tf32(v.z));
            sKc[base + 12] = __uint_as_float(cvt_tf32(v.w));
        }
#pragma unroll
        for (int p = 0; p < 4; p++) {
            int idx = (p << 8) + tid;
            int key = idx >> 4, dq = idx & 15;
            float4 v = *(const float4*)&vbase[(size_t)((c << 6) + key) * 64 + (dq << 2)];
            int d0 = dq << 2;
            int base = ((((key >> 3) << 2) + (dq >> 2)) << 7)
                     + ((key >> 2) & 1) + (((dq >> 1) & 1) << 1)
                     + (((d0 & 7) << 2) + (key & 3)) * 4;
            sVc[base + 0]  = __uint_as_float(cvt_tf32(v.x));
            sVc[base + 16] = __uint_as_float(cvt_tf32(v.y));
            sVc[base + 32] = __uint_as_float(cvt_tf32(v.z));
            sVc[base + 48] = __uint_as_float(cvt_tf32(v.w));
        }
    };

    // ---- stage Q once (A-frag layout, pre-scaled by 1/sqrt(D)=0.125) ----
#pragma unroll
    for (int p = 0; p < 16; p++) {
        int idx = (p << 8) + tid;       // float4 unit 0..4095
        int r = idx >> 4, dq = idx & 15;
        float4 v = *(const float4*)&qbase[(size_t)r * 64 + (dq << 2)];
        int base = ((((r >> 4) << 3) + (dq >> 1)) << 7) + ((r & 7) << 4)
                 + ((r >> 3) & 1) + ((dq & 1) << 1);
        sQ[base + 0]  = __uint_as_float(cvt_tf32(v.x * 0.125f));
        sQ[base + 4]  = __uint_as_float(cvt_tf32(v.y * 0.125f));
        sQ[base + 8]  = __uint_as_float(cvt_tf32(v.z * 0.125f));
        sQ[base + 12] = __uint_as_float(cvt_tf32(v.w * 0.125f));
    }
    stage(0, 0);

    float cO[2][8][4];
#pragma unroll
    for (int mi = 0; mi < 2; mi++)
#pragma unroll
        for (int f = 0; f < 8; f++)
#pragma unroll
            for (int q = 0; q < 4; q++) cO[mi][f][q] = 0.f;
    float mr[2][2], lr[2][2];
#pragma unroll
    for (int mi = 0; mi < 2; mi++) {
        mr[mi][0] = -1e30f; mr[mi][1] = -1e30f;
        lr[mi][0] = 0.f;    lr[mi][1] = 0.f;
    }

    int bufc = 0;
    for (int c = 0; c < 8; c++) {
        if (c < 7) {
            int bn = bufc + 1; if (bn == 3) bn = 0;
            stage(c + 1, bn);
        }
        __syncthreads();
        const float* sKc = sK + bufc * 4096;
        const float* sVc = sV + bufc * 4096;

        // ---- S = Q K^T (pre-scaled): 2 m-tiles x 8 n-tiles ----
        float cS[2][8][4];
#pragma unroll
        for (int mi = 0; mi < 2; mi++)
#pragma unroll
            for (int f = 0; f < 8; f++)
#pragma unroll
                for (int q = 0; q < 4; q++) cS[mi][f][q] = 0.f;
#pragma unroll
        for (int tkd = 0; tkd < 8; tkd++) {
            uint4 qa[2];
#pragma unroll
            for (int mi = 0; mi < 2; mi++)
                qa[mi] = *(const uint4*)&sQ[(((((wid << 1) + mi) << 3) + tkd) << 7)
                                            + (lane << 2)];
#pragma unroll
            for (int tn2 = 0; tn2 < 4; tn2++) {
                uint4 kb = *(const uint4*)&sKc[(((tkd << 2) + tn2) << 7) + (lane << 2)];
#pragma unroll
                for (int mi = 0; mi < 2; mi++) {
                    mma_tf32(cS[mi][tn2 * 2],     qa[mi].x, qa[mi].y, qa[mi].z,
                             qa[mi].w, kb.x, kb.y);
                    mma_tf32(cS[mi][tn2 * 2 + 1], qa[mi].x, qa[mi].y, qa[mi].z,
                             qa[mi].w, kb.z, kb.w);
                }
            }
        }

        // ---- online softmax per m-tile (rows gid, gid+8) ----
#pragma unroll
        for (int mi = 0; mi < 2; mi++) {
            float smax0 = -1e30f, smax1 = -1e30f;
#pragma unroll
            for (int f = 0; f < 8; f++) {
                smax0 = fmaxf(smax0, fmaxf(cS[mi][f][0], cS[mi][f][1]));
                smax1 = fmaxf(smax1, fmaxf(cS[mi][f][2], cS[mi][f][3]));
            }
            smax0 = fmaxf(smax0, __shfl_xor_sync(0xffffffffu, smax0, 1));
            smax0 = fmaxf(smax0, __shfl_xor_sync(0xffffffffu, smax0, 2));
            smax1 = fmaxf(smax1, __shfl_xor_sync(0xffffffffu, smax1, 1));
            smax1 = fmaxf(smax1, __shfl_xor_sync(0xffffffffu, smax1, 2));
            float mn0 = fmaxf(mr[mi][0], smax0), mn1 = fmaxf(mr[mi][1], smax1);
            float corr0 = __expf(mr[mi][0] - mn0), corr1 = __expf(mr[mi][1] - mn1);
            mr[mi][0] = mn0; mr[mi][1] = mn1;
            float rs0 = 0.f, rs1 = 0.f;
#pragma unroll
            for (int f = 0; f < 8; f++) {
                float p0 = __expf(cS[mi][f][0] - mn0);
                float p1 = __expf(cS[mi][f][1] - mn0);
                float p2 = __expf(cS[mi][f][2] - mn1);
                float p3 = __expf(cS[mi][f][3] - mn1);
                rs0 += p0 + p1; rs1 += p2 + p3;
                cS[mi][f][0] = __uint_as_float(cvt_tf32(p0));
                cS[mi][f][1] = __uint_as_float(cvt_tf32(p1));
                cS[mi][f][2] = __uint_as_float(cvt_tf32(p2));
                cS[mi][f][3] = __uint_as_float(cvt_tf32(p3));
            }
            rs0 += __shfl_xor_sync(0xffffffffu, rs0, 1);
            rs0 += __shfl_xor_sync(0xffffffffu, rs0, 2);
            rs1 += __shfl_xor_sync(0xffffffffu, rs1, 1);
            rs1 += __shfl_xor_sync(0xffffffffu, rs1, 2);
            lr[mi][0] = lr[mi][0] * corr0 + rs0;
            lr[mi][1] = lr[mi][1] * corr1 + rs1;
#pragma unroll
            for (int f = 0; f < 8; f++) {
                cO[mi][f][0] *= corr0; cO[mi][f][1] *= corr0;
                cO[mi][f][2] *= corr1; cO[mi][f][3] *= corr1;
            }
        }

        // ---- O += P V : shfl P C-frag -> A-frag; V frags reused by both mi ----
        const int src  = (lane & 28) | (tig >> 1);
        const int src2 = src + 2;
        const bool odd = tig & 1;
#pragma unroll
        for (int kb = 0; kb < 8; kb++) {
            uint32_t pa[2][4];
#pragma unroll
            for (int mi = 0; mi < 2; mi++) {
                float v0 = __shfl_sync(0xffffffffu, cS[mi][kb][0], src);
                float v1 = __shfl_sync(0xffffffffu, cS[mi][kb][1], src);
                float v2 = __shfl_sync(0xffffffffu, cS[mi][kb][2], src);
                float v3 = __shfl_sync(0xffffffffu, cS[mi][kb][3], src);
                float w0 = __shfl_sync(0xffffffffu, cS[mi][kb][0], src2);
                float w1 = __shfl_sync(0xffffffffu, cS[mi][kb][1], src2);
                float w2 = __shfl_sync(0xffffffffu, cS[mi][kb][2], src2);
                float w3 = __shfl_sync(0xffffffffu, cS[mi][kb][3], src2);
                pa[mi][0] = __float_as_uint(odd ? v1 : v0);
                pa[mi][1] = __float_as_uint(odd ? v3 : v2);
                pa[mi][2] = __float_as_uint(odd ? w1 : w0);
                pa[mi][3] = __float_as_uint(odd ? w3 : w2);
            }
#pragma unroll
            for (int tn = 0; tn < 4; tn++) {
                uint4 vb = *(const uint4*)&sVc[(((kb << 2) + tn) << 7) + (lane << 2)];
#pragma unroll
                for (int mi = 0; mi < 2; mi++) {
                    mma_tf32(cO[mi][tn * 2],     pa[mi][0], pa[mi][1], pa[mi][2],
                             pa[mi][3], vb.x, vb.y);
                    mma_tf32(cO[mi][tn * 2 + 1], pa[mi][0], pa[mi][1], pa[mi][2],
                             pa[mi][3], vb.z, vb.w);
                }
            }
        }
        bufc++; if (bufc == 3) bufc = 0;
    }

    // ---- epilogue: 1/l and inverse-permutation scatter ----
    const int w = wh >> 3, h = wh & 7;
    const int wx = w >> 4, wy = (w >> 2) & 3, wz = w & 3;
#pragma unroll
    for (int mi = 0; mi < 2; mi++)
#pragma unroll
        for (int rr = 0; rr < 2; rr++) {
            int m = m0 + (wid << 5) + (mi << 4) + gid + (rr << 3);
            int mz = m >> 6, my = (m >> 3) & 7, mx = m & 7;
            int n = (wz * 8 + mz) * 1024 + (wy * 8 + my) * 32 + (wx * 8 + mx);
            float inv = 1.0f / lr[mi][rr];
            float* dsth = g_h + (size_t)n * 512 + h * 64 + (tig << 1);
#pragma unroll
            for (int f = 0; f < 8; f++)
                *(float2*)&dsth[f << 3] =
                    make_float2(cO[mi][f][2 * rr] * inv,
                                cO[mi][f][2 * rr + 1] * inv);
        }
}

// ---------------------------------------------------------------------------
// kernel_launch
// inputs: x_feats, coords, w_qkv, b_qkv, gamma_q, gamma_k, w_out, b_out
// ---------------------------------------------------------------------------
extern "C" void kernel_launch(void* const* d_in, const int* in_sizes, int n_in,
                              void* d_out, int out_size)
{
    (void)in_sizes; (void)n_in; (void)out_size;
    const float* x      = (const float*)d_in[0];
    const int*   coords = (const int*)  d_in[1];
    const float* wqkv   = (const float*)d_in[2];
    const float* bqkv   = (const float*)d_in[3];
    const float* gq     = (const float*)d_in[4];
    const float* gk     = (const float*)d_in[5];
    const float* wout   = (const float*)d_in[6];
    const float* bout   = (const float*)d_in[7];
    float* outp = (float*)d_out;

    cudaFuncSetAttribute(window_attn_mma,
                         cudaFuncAttributeMaxDynamicSharedMemorySize,
                         ATTN_SMEM_BYTES);

    float* wqkvT;  cudaGetSymbolAddress((void**)&wqkvT, g_wqkvT);
    float* woutT;  cudaGetSymbolAddress((void**)&woutT, g_woutT);
    float* hbuf;   cudaGetSymbolAddress((void**)&hbuf,  g_h);

    transpose_both<<<dim3(48, 16, 2), dim3(32, 8)>>>(wqkv, wqkvT, wout, woutT);
    gemm_mma<<<dim3(12, 256), 256>>>(x, wqkvT, bqkv, coords, gq, gk, nullptr, 0);
    window_attn_mma<<<dim3(2, 512), 256, ATTN_SMEM_BYTES>>>();
    gemm_mma<<<dim3(4, 256), 256>>>(hbuf, woutT, bout, nullptr, nullptr, nullptr,
                                    outp, 1);
}

// round 12
// speedup vs baseline: 2.1779x; 1.0397x over previous
#include <cuda_runtime.h>
#include <math.h>
#include <stdint.h>

// ---------------------------------------------------------------------------
// Problem constants: N=32768 tokens, C=512, H=8, D=64; 64 windows x 512 tokens
// ---------------------------------------------------------------------------

// Scratch (static device arrays; no allocations anywhere)
__device__ float g_q[64 * 8 * 512 * 64];   // [w][h][m][d]
__device__ float g_k[64 * 8 * 512 * 64];
__device__ float g_v[64 * 8 * 512 * 64];
__device__ float g_h[32768 * 512];         // [n][h*64+d] (inverse-permuted)
__device__ float g_wqkvP[12 * 16 * 4096];  // wqkv prepacked B-frag images
__device__ float g_woutP[4 * 16 * 4096];   // wout  prepacked B-frag images

// ---------------------------------------------------------------------------
// Helpers
// ---------------------------------------------------------------------------
__device__ __forceinline__ uint32_t cvt_tf32(float f) {
    uint32_t u; asm("cvt.rna.tf32.f32 %0, %1;" : "=r"(u) : "f"(f)); return u;
}

__device__ __forceinline__ void mma_tf32(float c[4], uint32_t a0, uint32_t a1,
                                         uint32_t a2, uint32_t a3,
                                         uint32_t b0, uint32_t b1) {
    asm volatile(
        "mma.sync.aligned.m16n8k8.row.col.f32.tf32.tf32.f32 "
        "{%0,%1,%2,%3}, {%4,%5,%6,%7}, {%8,%9}, {%0,%1,%2,%3};"
        : "+f"(c[0]), "+f"(c[1]), "+f"(c[2]), "+f"(c[3])
        : "r"(a0), "r"(a1), "r"(a2), "r"(a3), "r"(b0), "r"(b1));
}

// ---------------------------------------------------------------------------
// K0: prepack weights into B-fragment smem images (one-time, replaces
// transpose).  src is [512][jdim] row-major (k rows).  For tile J and chunk s
// the output block dst[(J*16+s)*4096 .. +4096) is byte-identical to what the
// old GEMM producer built in sB — same slot/lane/XOR algebra, same
// cvt.rna.tf32 values.  z=0: wqkv (jdim=1536, J<12); z=1: wout (jdim=512, J<4).
// ---------------------------------------------------------------------------
__global__ void prepack_b(const float* __restrict__ srcA,
                          float* __restrict__ dstA,
                          const float* __restrict__ srcB,
                          float* __restrict__ dstB)
{
    __shared__ float img[4096];
    const int z = blockIdx.z;
    if (z && blockIdx.x >= 4) return;
    const int jdim = z ? 512 : 1536;
    const float* src = z ? srcB : srcA;
    float* dst = z ? dstB : dstA;
    const int J = blockIdx.x, s = blockIdx.y;
    const int tid = threadIdx.x;

#pragma unroll
    for (int p = 0; p < 16; p++) {
        int idx = (p << 8) + tid;       // 0..4095
        int kk = idx >> 7;              // k within chunk, 0..31
        int n  = idx & 127;             // j within tile
        float v = src[(size_t)((s << 5) + kk) * jdim + (J << 7) + n];
        int kq = kk >> 2, e = kk & 3, tk = kq >> 1;
        int base = ((((n >> 4) << 2) + tk) << 7) + ((n & 7) << 4)
                 + (kq & 1) + (((n >> 3) & 1) << 1);
        img[base + ((e ^ tk) << 2)] = __uint_as_float(cvt_tf32(v));
    }
    __syncthreads();
    float* out = dst + ((size_t)(J * 16 + s) << 12);
#pragma unroll
    for (int p = 0; p < 4; p++) {
        int i4 = (p << 8) + tid;        // float4 unit 0..1023
        *(float4*)&out[i4 << 2] = *(const float4*)&img[i4 << 2];
    }
}

// ---------------------------------------------------------------------------
// tf32 mma.sync GEMM (R6-validated local optimum): C[128,128] tile, K=512,
// chunk 32, static smem, 2 CTAs/SM.  B now streamed from prepacked fragment
// images (straight LDG.128 -> STS.128 copy; no swizzle math, no cvt).
// Do NOT add register-live state (R7/R10) or in-CTA pipelining (R9).
// ---------------------------------------------------------------------------
__global__ __launch_bounds__(256, 2)
void gemm_mma(const float* __restrict__ A, const float* __restrict__ BP,
              const float* __restrict__ bias, const int* __restrict__ coords,
              const float* __restrict__ gq, const float* __restrict__ gk,
              float* __restrict__ outp, int mode)
{
    __shared__ float sA[4096];
    __shared__ float sB[4096];
    __shared__ float sBias[128];
    __shared__ float sGam[128];
    __shared__ float sRed[128][4];

    const int tid = threadIdx.x;
    const int lane = tid & 31, wid = tid >> 5;
    const int wm = wid & 1, wn = wid >> 1;
    const int gid = lane >> 2, tig = lane & 3;
    const int m0 = blockIdx.y << 7;
    const int j0 = blockIdx.x << 7;
    const int sec = j0 >> 9;

    if (tid < 128) {
        sBias[tid] = bias[j0 + tid];
        float g = 1.0f;
        if (mode == 0) {
            if (sec == 0) g = gq[(j0 & 511) + tid];
            else if (sec == 1) g = gk[(j0 & 511) + tid];
        }
        sGam[tid] = g;
    }

    float c[4][4][4];
#pragma unroll
    for (int mi = 0; mi < 4; mi++)
#pragma unroll
        for (int ni = 0; ni < 4; ni++)
#pragma unroll
            for (int q = 0; q < 4; q++) c[mi][ni][q] = 0.f;

    const float* bBase = BP + ((size_t)blockIdx.x << 16);   // J * 16 chunks * 4096

    for (int s = 0; s < 16; s++) {
        const int kb = s << 5;
        if (s) __syncthreads();
        // ---- stage A (fragment layout + cvt, unchanged) ----
#pragma unroll
        for (int p = 0; p < 4; p++) {
            int idx = (p << 8) + tid;
            int r = idx >> 3, cq = idx & 7;
            int tk = cq >> 1;
            float4 v = *(const float4*)&A[(size_t)(m0 + r) * 512 + kb + (cq << 2)];
            int base = ((((r >> 4) << 2) + tk) << 7) + ((r & 7) << 4)
                     + ((r >> 3) & 1) + ((cq & 1) << 1);
            sA[base + ((0 ^ tk) << 2)] = __uint_as_float(cvt_tf32(v.x));
            sA[base + ((1 ^ tk) << 2)] = __uint_as_float(cvt_tf32(v.y));
            sA[base + ((2 ^ tk) << 2)] = __uint_as_float(cvt_tf32(v.z));
            sA[base + ((3 ^ tk) << 2)] = __uint_as_float(cvt_tf32(v.w));
        }
        // ---- stage B: straight copy from prepacked fragment image ----
        {
            const float* bsrc = bBase + ((size_t)s << 12);
#pragma unroll
            for (int p = 0; p < 4; p++) {
                int i4 = (p << 8) + tid;
                *(float4*)&sB[i4 << 2] = *(const float4*)&bsrc[i4 << 2];
            }
        }
        __syncthreads();
#pragma unroll
        for (int tk = 0; tk < 4; tk++) {
            const int lx = ((lane ^ tk) << 2);
            uint4 a[4];
#pragma unroll
            for (int mi = 0; mi < 4; mi++)
                a[mi] = *(const uint4*)&sA[(((((wm << 2) + mi) << 2) + tk) << 7) + lx];
            uint4 b[2];
#pragma unroll
            for (int pi = 0; pi < 2; pi++)
                b[pi] = *(const uint4*)&sB[(((((wn << 1) + pi) << 2) + tk) << 7) + lx];
#pragma unroll
            for (int mi = 0; mi < 4; mi++)
#pragma unroll
                for (int pi = 0; pi < 2; pi++) {
                    mma_tf32(c[mi][pi * 2],     a[mi].x, a[mi].y, a[mi].z, a[mi].w,
                             b[pi].x, b[pi].y);
                    mma_tf32(c[mi][pi * 2 + 1], a[mi].x, a[mi].y, a[mi].z, a[mi].w,
                             b[pi].z, b[pi].w);
                }
        }
    }

    if (mode == 1) {
#pragma unroll
        for (int mi = 0; mi < 4; mi++)
#pragma unroll
            for (int ni = 0; ni < 4; ni++) {
                int col = (wn << 5) + (ni << 3) + (tig << 1);
                int rlo = m0 + (wm << 6) + (mi << 4) + gid;
                float2 v0 = make_float2(c[mi][ni][0] + sBias[col],
                                        c[mi][ni][1] + sBias[col + 1]);
                float2 v1 = make_float2(c[mi][ni][2] + sBias[col],
                                        c[mi][ni][3] + sBias[col + 1]);
                *(float2*)&outp[(size_t)rlo * 512 + j0 + col] = v0;
                *(float2*)&outp[(size_t)(rlo + 8) * 512 + j0 + col] = v1;
            }
        return;
    }

#pragma unroll
    for (int mi = 0; mi < 4; mi++)
#pragma unroll
        for (int ni = 0; ni < 4; ni++) {
            int col = (wn << 5) + (ni << 3) + (tig << 1);
            c[mi][ni][0] += sBias[col];
            c[mi][ni][1] += sBias[col + 1];
            c[mi][ni][2] += sBias[col];
            c[mi][ni][3] += sBias[col + 1];
        }

    if (sec < 2) {
#pragma unroll
        for (int mi = 0; mi < 4; mi++)
#pragma unroll
            for (int h = 0; h < 2; h++) {
                float ss = 0.f;
#pragma unroll
                for (int ni = 0; ni < 4; ni++) {
                    float x0 = c[mi][ni][2 * h], x1 = c[mi][ni][2 * h + 1];
                    ss += x0 * x0 + x1 * x1;
                }
                ss += __shfl_xor_sync(0xffffffffu, ss, 1);
                ss += __shfl_xor_sync(0xffffffffu, ss, 2);
                if (tig == 0)
                    sRed[(wm << 6) + (mi << 4) + gid + (h << 3)][wn] = ss;
            }
        __syncthreads();
#pragma unroll
        for (int mi = 0; mi < 4; mi++)
#pragma unroll
            for (int h = 0; h < 2; h++) {
                int rl = (wm << 6) + (mi << 4) + gid + (h << 3);
                float tot = sRed[rl][wn] + sRed[rl][wn ^ 1];
                float inv = 8.0f / fmaxf(sqrtf(tot), 1e-12f);
#pragma unroll
                for (int ni = 0; ni < 4; ni++) {
                    int col = (wn << 5) + (ni << 3) + (tig << 1);
                    c[mi][ni][2 * h]     *= inv * sGam[col];
                    c[mi][ni][2 * h + 1] *= inv * sGam[col + 1];
                }
            }
    }

    float* dst = (sec == 0) ? g_q : ((sec == 1) ? g_k : g_v);
    const int head = ((j0 & 511) >> 6) + (wn >> 1);
    const int dbase = ((wn & 1) << 5) + (tig << 1);
#pragma unroll
    for (int mi = 0; mi < 4; mi++)
#pragma unroll
        for (int h = 0; h < 2; h++) {
            int token = m0 + (wm << 6) + (mi << 4) + gid + (h << 3);
            int cx = coords[4 * token + 1];
            int cy = coords[4 * token + 2];
            int cz = coords[4 * token + 3];
            int w = ((cx >> 3) << 4) + ((cy >> 3) << 2) + (cz >> 3);
            int m = ((cz & 7) << 6) + ((cy & 7) << 3) + (cx & 7);
            size_t bb = ((size_t)((w << 3) + head) * 512 + m) * 64 + dbase;
#pragma unroll
            for (int ni = 0; ni < 4; ni++)
                *(float2*)&dst[bb + (ni << 3)] =
                    make_float2(c[mi][ni][2 * h], c[mi][ni][2 * h + 1]);
        }
}

// ---------------------------------------------------------------------------
// K2: window attention via tf32 mma.sync — 32-row warp tiles + triple-buffered
// K/V fragment smem, one barrier per chunk (R8-validated, unchanged).
// ---------------------------------------------------------------------------
#define ATTN_SMEM_BYTES ((8192 * 2 + 3 * 4096 + 3 * 4096) * 4)

__global__ __launch_bounds__(256, 1)
void window_attn_mma()
{
    extern __shared__ float sm[];
    float* sQ = sm;              // 16384 floats: 128 frag tiles (mt*8 + tkd)
    float* sK = sm + 16384;      // 3 x 4096 floats
    float* sV = sm + 16384 + 3 * 4096;   // 3 x 4096 floats

    const int tid = threadIdx.x;
    const int lane = tid & 31, wid = tid >> 5;
    const int gid = lane >> 2, tig = lane & 3;
    const int qt = blockIdx.x;          // 0..1
    const int wh = blockIdx.y;          // w*8 + h
    const int m0 = qt << 8;             // 256 rows per CTA

    const float* qbase = g_q + ((size_t)wh * 512 + m0) * 64;
    const float* kbase = g_k + (size_t)wh * 512 * 64;
    const float* vbase = g_v + (size_t)wh * 512 * 64;

    auto stage = [&](int c, int bi) {
        float* sKc = sK + bi * 4096;
        float* sVc = sV + bi * 4096;
#pragma unroll
        for (int p = 0; p < 4; p++) {
            int idx = (p << 8) + tid;       // float4 unit 0..1023
            int key = idx >> 4, dq = idx & 15;
            float4 v = *(const float4*)&kbase[(size_t)((c << 6) + key) * 64 + (dq << 2)];
            int base = ((((dq >> 1) << 2) + (key >> 4)) << 7) + ((key & 7) << 4)
                     + (dq & 1) + (((key >> 3) & 1) << 1);
            sKc[base + 0]  = __uint_as_float(cvt_tf32(v.x));
            sKc[base + 4]  = __uint_as_float(cvt_tf32(v.y));
            sKc[base + 8]  = __uint_as_float(cvt_tf32(v.z));
            sKc[base + 12] = __uint_as_float(cvt_tf32(v.w));
        }
#pragma unroll
        for (int p = 0; p < 4; p++) {
            int idx = (p << 8) + tid;
            int key = idx >> 4, dq = idx & 15;
            float4 v = *(const float4*)&vbase[(size_t)((c << 6) + key) * 64 + (dq << 2)];
            int d0 = dq << 2;
            int base = ((((key >> 3) << 2) + (dq >> 2)) << 7)
                     + ((key >> 2) & 1) + (((dq >> 1) & 1) << 1)
                     + (((d0 & 7) << 2) + (key & 3)) * 4;
            sVc[base + 0]  = __uint_as_float(cvt_tf32(v.x));
            sVc[base + 16] = __uint_as_float(cvt_tf32(v.y));
            sVc[base + 32] = __uint_as_float(cvt_tf32(v.z));
            sVc[base + 48] = __uint_as_float(cvt_tf32(v.w));
        }
    };

    // ---- stage Q once (A-frag layout, pre-scaled by 1/sqrt(D)=0.125) ----
#pragma unroll
    for (int p = 0; p < 16; p++) {
        int idx = (p << 8) + tid;       // float4 unit 0..4095
        int r = idx >> 4, dq = idx & 15;
        float4 v = *(const float4*)&qbase[(size_t)r * 64 + (dq << 2)];
        int base = ((((r >> 4) << 3) + (dq >> 1)) << 7) + ((r & 7) << 4)
                 + ((r >> 3) & 1) + ((dq & 1) << 1);
        sQ[base + 0]  = __uint_as_float(cvt_tf32(v.x * 0.125f));
        sQ[base + 4]  = __uint_as_float(cvt_tf32(v.y * 0.125f));
        sQ[base + 8]  = __uint_as_float(cvt_tf32(v.z * 0.125f));
        sQ[base + 12] = __uint_as_float(cvt_tf32(v.w * 0.125f));
    }
    stage(0, 0);

    float cO[2][8][4];
#pragma unroll
    for (int mi = 0; mi < 2; mi++)
#pragma unroll
        for (int f = 0; f < 8; f++)
#pragma unroll
            for (int q = 0; q < 4; q++) cO[mi][f][q] = 0.f;
    float mr[2][2], lr[2][2];
#pragma unroll
    for (int mi = 0; mi < 2; mi++) {
        mr[mi][0] = -1e30f; mr[mi][1] = -1e30f;
        lr[mi][0] = 0.f;    lr[mi][1] = 0.f;
    }

    int bufc = 0;
    for (int c = 0; c < 8; c++) {
        if (c < 7) {
            int bn = bufc + 1; if (bn == 3) bn = 0;
            stage(c + 1, bn);
        }
        __syncthreads();
        const float* sKc = sK + bufc * 4096;
        const float* sVc = sV + bufc * 4096;

        // ---- S = Q K^T (pre-scaled): 2 m-tiles x 8 n-tiles ----
        float cS[2][8][4];
#pragma unroll
        for (int mi = 0; mi < 2; mi++)
#pragma unroll
            for (int f = 0; f < 8; f++)
#pragma unroll
                for (int q = 0; q < 4; q++) cS[mi][f][q] = 0.f;
#pragma unroll
        for (int tkd = 0; tkd < 8; tkd++) {
            uint4 qa[2];
#pragma unroll
            for (int mi = 0; mi < 2; mi++)
                qa[mi] = *(const uint4*)&sQ[(((((wid << 1) + mi) << 3) + tkd) << 7)
                                            + (lane << 2)];
#pragma unroll
            for (int tn2 = 0; tn2 < 4; tn2++) {
                uint4 kb = *(const uint4*)&sKc[(((tkd << 2) + tn2) << 7) + (lane << 2)];
#pragma unroll
                for (int mi = 0; mi < 2; mi++) {
                    mma_tf32(cS[mi][tn2 * 2],     qa[mi].x, qa[mi].y, qa[mi].z,
                             qa[mi].w, kb.x, kb.y);
                    mma_tf32(cS[mi][tn2 * 2 + 1], qa[mi].x, qa[mi].y, qa[mi].z,
                             qa[mi].w, kb.z, kb.w);
                }
            }
        }

        // ---- online softmax per m-tile (rows gid, gid+8) ----
#pragma unroll
        for (int mi = 0; mi < 2; mi++) {
            float smax0 = -1e30f, smax1 = -1e30f;
#pragma unroll
            for (int f = 0; f < 8; f++) {
                smax0 = fmaxf(smax0, fmaxf(cS[mi][f][0], cS[mi][f][1]));
                smax1 = fmaxf(smax1, fmaxf(cS[mi][f][2], cS[mi][f][3]));
            }
            smax0 = fmaxf(smax0, __shfl_xor_sync(0xffffffffu, smax0, 1));
            smax0 = fmaxf(smax0, __shfl_xor_sync(0xffffffffu, smax0, 2));
            smax1 = fmaxf(smax1, __shfl_xor_sync(0xffffffffu, smax1, 1));
            smax1 = fmaxf(smax1, __shfl_xor_sync(0xffffffffu, smax1, 2));
            float mn0 = fmaxf(mr[mi][0], smax0), mn1 = fmaxf(mr[mi][1], smax1);
            float corr0 = __expf(mr[mi][0] - mn0), corr1 = __expf(mr[mi][1] - mn1);
            mr[mi][0] = mn0; mr[mi][1] = mn1;
            float rs0 = 0.f, rs1 = 0.f;
#pragma unroll
            for (int f = 0; f < 8; f++) {
                float p0 = __expf(cS[mi][f][0] - mn0);
                float p1 = __expf(cS[mi][f][1] - mn0);
                float p2 = __expf(cS[mi][f][2] - mn1);
                float p3 = __expf(cS[mi][f][3] - mn1);
                rs0 += p0 + p1; rs1 += p2 + p3;
                cS[mi][f][0] = __uint_as_float(cvt_tf32(p0));
                cS[mi][f][1] = __uint_as_float(cvt_tf32(p1));
                cS[mi][f][2] = __uint_as_float(cvt_tf32(p2));
                cS[mi][f][3] = __uint_as_float(cvt_tf32(p3));
            }
            rs0 += __shfl_xor_sync(0xffffffffu, rs0, 1);
            rs0 += __shfl_xor_sync(0xffffffffu, rs0, 2);
            rs1 += __shfl_xor_sync(0xffffffffu, rs1, 1);
            rs1 += __shfl_xor_sync(0xffffffffu, rs1, 2);
            lr[mi][0] = lr[mi][0] * corr0 + rs0;
            lr[mi][1] = lr[mi][1] * corr1 + rs1;
#pragma unroll
            for (int f = 0; f < 8; f++) {
                cO[mi][f][0] *= corr0; cO[mi][f][1] *= corr0;
                cO[mi][f][2] *= corr1; cO[mi][f][3] *= corr1;
            }
        }

        // ---- O += P V : shfl P C-frag -> A-frag; V frags reused by both mi ----
        const int src  = (lane & 28) | (tig >> 1);
        const int src2 = src + 2;
        const bool odd = tig & 1;
#pragma unroll
        for (int kb = 0; kb < 8; kb++) {
            uint32_t pa[2][4];
#pragma unroll
            for (int mi = 0; mi < 2; mi++) {
                float v0 = __shfl_sync(0xffffffffu, cS[mi][kb][0], src);
                float v1 = __shfl_sync(0xffffffffu, cS[mi][kb][1], src);
                float v2 = __shfl_sync(0xffffffffu, cS[mi][kb][2], src);
                float v3 = __shfl_sync(0xffffffffu, cS[mi][kb][3], src);
                float w0 = __shfl_sync(0xffffffffu, cS[mi][kb][0], src2);
                float w1 = __shfl_sync(0xffffffffu, cS[mi][kb][1], src2);
                float w2 = __shfl_sync(0xffffffffu, cS[mi][kb][2], src2);
                float w3 = __shfl_sync(0xffffffffu, cS[mi][kb][3], src2);
                pa[mi][0] = __float_as_uint(odd ? v1 : v0);
                pa[mi][1] = __float_as_uint(odd ? v3 : v2);
                pa[mi][2] = __float_as_uint(odd ? w1 : w0);
                pa[mi][3] = __float_as_uint(odd ? w3 : w2);
            }
#pragma unroll
            for (int tn = 0; tn < 4; tn++) {
                uint4 vb = *(const uint4*)&sVc[(((kb << 2) + tn) << 7) + (lane << 2)];
#pragma unroll
                for (int mi = 0; mi < 2; mi++) {
                    mma_tf32(cO[mi][tn * 2],     pa[mi][0], pa[mi][1], pa[mi][2],
                             pa[mi][3], vb.x, vb.y);
                    mma_tf32(cO[mi][tn * 2 + 1], pa[mi][0], pa[mi][1], pa[mi][2],
                             pa[mi][3], vb.z, vb.w);
                }
            }
        }
        bufc++; if (bufc == 3) bufc = 0;
    }

    // ---- epilogue: 1/l and inverse-permutation scatter ----
    const int w = wh >> 3, h = wh & 7;
    const int wx = w >> 4, wy = (w >> 2) & 3, wz = w & 3;
#pragma unroll
    for (int mi = 0; mi < 2; mi++)
#pragma unroll
        for (int rr = 0; rr < 2; rr++) {
            int m = m0 + (wid << 5) + (mi << 4) + gid + (rr << 3);
            int mz = m >> 6, my = (m >> 3) & 7, mx = m & 7;
            int n = (wz * 8 + mz) * 1024 + (wy * 8 + my) * 32 + (wx * 8 + mx);
            float inv = 1.0f / lr[mi][rr];
            float* dsth = g_h + (size_t)n * 512 + h * 64 + (tig << 1);
#pragma unroll
            for (int f = 0; f < 8; f++)
                *(float2*)&dsth[f << 3] =
                    make_float2(cO[mi][f][2 * rr] * inv,
                                cO[mi][f][2 * rr + 1] * inv);
        }
}

// ---------------------------------------------------------------------------
// kernel_launch
// inputs: x_feats, coords, w_qkv, b_qkv, gamma_q, gamma_k, w_out, b_out
// ---------------------------------------------------------------------------
extern "C" void kernel_launch(void* const* d_in, const int* in_sizes, int n_in,
                              void* d_out, int out_size)
{
    (void)in_sizes; (void)n_in; (void)out_size;
    const float* x      = (const float*)d_in[0];
    const int*   coords = (const int*)  d_in[1];
    const float* wqkv   = (const float*)d_in[2];
    const float* bqkv   = (const float*)d_in[3];
    const float* gq     = (const float*)d_in[4];
    const float* gk     = (const float*)d_in[5];
    const float* wout   = (const float*)d_in[6];
    const float* bout   = (const float*)d_in[7];
    float* outp = (float*)d_out;

    cudaFuncSetAttribute(window_attn_mma,
                         cudaFuncAttributeMaxDynamicSharedMemorySize,
                         ATTN_SMEM_BYTES);

    float* wqkvP;  cudaGetSymbolAddress((void**)&wqkvP, g_wqkvP);
    float* woutP;  cudaGetSymbolAddress((void**)&woutP, g_woutP);
    float* hbuf;   cudaGetSymbolAddress((void**)&hbuf,  g_h);

    prepack_b<<<dim3(12, 16, 2), 256>>>(wqkv, wqkvP, wout, woutP);
    gemm_mma<<<dim3(12, 256), 256>>>(x, wqkvP, bqkv, coords, gq, gk, nullptr, 0);
    window_attn_mma<<<dim3(2, 512), 256, ATTN_SMEM_BYTES>>>();
    gemm_mma<<<dim3(4, 256), 256>>>(hbuf, woutP, bout, nullptr, nullptr, nullptr,
                                    outp, 1);
}

// round 13
// speedup vs baseline: 2.3036x; 1.0577x over previous
#include <cuda_runtime.h>
#include <math.h>
#include <stdint.h>

// ---------------------------------------------------------------------------
// Problem constants: N=32768 tokens, C=512, H=8, D=64; 64 windows x 512 tokens
// ---------------------------------------------------------------------------
// g_q: per (wh, qt<2) a 16384-float A-frag image (Q pre-scaled+cvt'd)
// g_k: per (wh, chunk<8) a 4096-float B-frag image (cvt'd)
// g_v: per (wh, chunk<8) a 4096-float PV-frag image (cvt'd)
__device__ float g_q[512 * 2 * 16384];
__device__ float g_k[512 * 8 * 4096];
__device__ float g_v[512 * 8 * 4096];
__device__ float g_h[32768 * 512];         // [n][h*64+d] (inverse-permuted)
__device__ float g_wqkvP[12 * 16 * 4096];  // wqkv prepacked B-frag images
__device__ float g_woutP[4 * 16 * 4096];   // wout  prepacked B-frag images

// ---------------------------------------------------------------------------
// Helpers
// ---------------------------------------------------------------------------
__device__ __forceinline__ uint32_t cvt_tf32(float f) {
    uint32_t u; asm("cvt.rna.tf32.f32 %0, %1;" : "=r"(u) : "f"(f)); return u;
}

__device__ __forceinline__ void mma_tf32(float c[4], uint32_t a0, uint32_t a1,
                                         uint32_t a2, uint32_t a3,
                                         uint32_t b0, uint32_t b1) {
    asm volatile(
        "mma.sync.aligned.m16n8k8.row.col.f32.tf32.tf32.f32 "
        "{%0,%1,%2,%3}, {%4,%5,%6,%7}, {%8,%9}, {%0,%1,%2,%3};"
        : "+f"(c[0]), "+f"(c[1]), "+f"(c[2]), "+f"(c[3])
        : "r"(a0), "r"(a1), "r"(a2), "r"(a3), "r"(b0), "r"(b1));
}

// ---------------------------------------------------------------------------
// K0: prepack weights into B-fragment smem images (R12-validated).
// ---------------------------------------------------------------------------
__global__ void prepack_b(const float* __restrict__ srcA,
                          float* __restrict__ dstA,
                          const float* __restrict__ srcB,
                          float* __restrict__ dstB)
{
    __shared__ float img[4096];
    const int z = blockIdx.z;
    if (z && blockIdx.x >= 4) return;
    const int jdim = z ? 512 : 1536;
    const float* src = z ? srcB : srcA;
    float* dst = z ? dstB : dstA;
    const int J = blockIdx.x, s = blockIdx.y;
    const int tid = threadIdx.x;

#pragma unroll
    for (int p = 0; p < 16; p++) {
        int idx = (p << 8) + tid;       // 0..4095
        int kk = idx >> 7;              // k within chunk, 0..31
        int n  = idx & 127;             // j within tile
        float v = src[(size_t)((s << 5) + kk) * jdim + (J << 7) + n];
        int kq = kk >> 2, e = kk & 3, tk = kq >> 1;
        int base = ((((n >> 4) << 2) + tk) << 7) + ((n & 7) << 4)
                 + (kq & 1) + (((n >> 3) & 1) << 1);
        img[base + ((e ^ tk) << 2)] = __uint_as_float(cvt_tf32(v));
    }
    __syncthreads();
    float* out = dst + ((size_t)(J * 16 + s) << 12);
#pragma unroll
    for (int p = 0; p < 4; p++) {
        int i4 = (p << 8) + tid;        // float4 unit 0..1023
        *(float4*)&out[i4 << 2] = *(const float4*)&img[i4 << 2];
    }
}

// ---------------------------------------------------------------------------
// tf32 mma.sync GEMM (R6/R12-validated): C[128,128] tile, K=512, chunk 32,
// static smem, 2 CTAs/SM, B streamed from prepacked fragment images.
// mode 0 epilogue now writes q/k/v DIRECTLY as attention fragment images
// (same values as before: identical fp32 in, identical cvt order).
// ---------------------------------------------------------------------------
__global__ __launch_bounds__(256, 2)
void gemm_mma(const float* __restrict__ A, const float* __restrict__ BP,
              const float* __restrict__ bias, const int* __restrict__ coords,
              const float* __restrict__ gq, const float* __restrict__ gk,
              float* __restrict__ outp, int mode)
{
    __shared__ float sA[4096];
    __shared__ float sB[4096];
    __shared__ float sBias[128];
    __shared__ float sGam[128];
    __shared__ float sRed[128][4];

    const int tid = threadIdx.x;
    const int lane = tid & 31, wid = tid >> 5;
    const int wm = wid & 1, wn = wid >> 1;
    const int gid = lane >> 2, tig = lane & 3;
    const int m0 = blockIdx.y << 7;
    const int j0 = blockIdx.x << 7;
    const int sec = j0 >> 9;

    if (tid < 128) {
        sBias[tid] = bias[j0 + tid];
        float g = 1.0f;
        if (mode == 0) {
            if (sec == 0) g = gq[(j0 & 511) + tid];
            else if (sec == 1) g = gk[(j0 & 511) + tid];
        }
        sGam[tid] = g;
    }

    float c[4][4][4];
#pragma unroll
    for (int mi = 0; mi < 4; mi++)
#pragma unroll
        for (int ni = 0; ni < 4; ni++)
#pragma unroll
            for (int q = 0; q < 4; q++) c[mi][ni][q] = 0.f;

    const float* bBase = BP + ((size_t)blockIdx.x << 16);

    for (int s = 0; s < 16; s++) {
        const int kb = s << 5;
        if (s) __syncthreads();
#pragma unroll
        for (int p = 0; p < 4; p++) {
            int idx = (p << 8) + tid;
            int r = idx >> 3, cq = idx & 7;
            int tk = cq >> 1;
            float4 v = *(const float4*)&A[(size_t)(m0 + r) * 512 + kb + (cq << 2)];
            int base = ((((r >> 4) << 2) + tk) << 7) + ((r & 7) << 4)
                     + ((r >> 3) & 1) + ((cq & 1) << 1);
            sA[base + ((0 ^ tk) << 2)] = __uint_as_float(cvt_tf32(v.x));
            sA[base + ((1 ^ tk) << 2)] = __uint_as_float(cvt_tf32(v.y));
            sA[base + ((2 ^ tk) << 2)] = __uint_as_float(cvt_tf32(v.z));
            sA[base + ((3 ^ tk) << 2)] = __uint_as_float(cvt_tf32(v.w));
        }
        {
            const float* bsrc = bBase + ((size_t)s << 12);
#pragma unroll
            for (int p = 0; p < 4; p++) {
                int i4 = (p << 8) + tid;
                *(float4*)&sB[i4 << 2] = *(const float4*)&bsrc[i4 << 2];
            }
        }
        __syncthreads();
#pragma unroll
        for (int tk = 0; tk < 4; tk++) {
            const int lx = ((lane ^ tk) << 2);
            uint4 a[4];
#pragma unroll
            for (int mi = 0; mi < 4; mi++)
                a[mi] = *(const uint4*)&sA[(((((wm << 2) + mi) << 2) + tk) << 7) + lx];
            uint4 b[2];
#pragma unroll
            for (int pi = 0; pi < 2; pi++)
                b[pi] = *(const uint4*)&sB[(((((wn << 1) + pi) << 2) + tk) << 7) + lx];
#pragma unroll
            for (int mi = 0; mi < 4; mi++)
#pragma unroll
                for (int pi = 0; pi < 2; pi++) {
                    mma_tf32(c[mi][pi * 2],     a[mi].x, a[mi].y, a[mi].z, a[mi].w,
                             b[pi].x, b[pi].y);
                    mma_tf32(c[mi][pi * 2 + 1], a[mi].x, a[mi].y, a[mi].z, a[mi].w,
                             b[pi].z, b[pi].w);
                }
        }
    }

    if (mode == 1) {
#pragma unroll
        for (int mi = 0; mi < 4; mi++)
#pragma unroll
            for (int ni = 0; ni < 4; ni++) {
                int col = (wn << 5) + (ni << 3) + (tig << 1);
                int rlo = m0 + (wm << 6) + (mi << 4) + gid;
                float2 v0 = make_float2(c[mi][ni][0] + sBias[col],
                                        c[mi][ni][1] + sBias[col + 1]);
                float2 v1 = make_float2(c[mi][ni][2] + sBias[col],
                                        c[mi][ni][3] + sBias[col + 1]);
                *(float2*)&outp[(size_t)rlo * 512 + j0 + col] = v0;
                *(float2*)&outp[(size_t)(rlo + 8) * 512 + j0 + col] = v1;
            }
        return;
    }

    // ---- mode 0: bias ----
#pragma unroll
    for (int mi = 0; mi < 4; mi++)
#pragma unroll
        for (int ni = 0; ni < 4; ni++) {
            int col = (wn << 5) + (ni << 3) + (tig << 1);
            c[mi][ni][0] += sBias[col];
            c[mi][ni][1] += sBias[col + 1];
            c[mi][ni][2] += sBias[col];
            c[mi][ni][3] += sBias[col + 1];
        }

    if (sec < 2) {
#pragma unroll
        for (int mi = 0; mi < 4; mi++)
#pragma unroll
            for (int h = 0; h < 2; h++) {
                float ss = 0.f;
#pragma unroll
                for (int ni = 0; ni < 4; ni++) {
                    float x0 = c[mi][ni][2 * h], x1 = c[mi][ni][2 * h + 1];
                    ss += x0 * x0 + x1 * x1;
                }
                ss += __shfl_xor_sync(0xffffffffu, ss, 1);
                ss += __shfl_xor_sync(0xffffffffu, ss, 2);
                if (tig == 0)
                    sRed[(wm << 6) + (mi << 4) + gid + (h << 3)][wn] = ss;
            }
        __syncthreads();
#pragma unroll
        for (int mi = 0; mi < 4; mi++)
#pragma unroll
            for (int h = 0; h < 2; h++) {
                int rl = (wm << 6) + (mi << 4) + gid + (h << 3);
                float tot = sRed[rl][wn] + sRed[rl][wn ^ 1];
                float inv = 8.0f / fmaxf(sqrtf(tot), 1e-12f);
#pragma unroll
                for (int ni = 0; ni < 4; ni++) {
                    int col = (wn << 5) + (ni << 3) + (tig << 1);
                    c[mi][ni][2 * h]     *= inv * sGam[col];
                    c[mi][ni][2 * h + 1] *= inv * sGam[col + 1];
                }
            }
    }

    // ---- scatter directly into attention fragment images ----
    const int head = ((j0 & 511) >> 6) + (wn >> 1);
    const int dbase = ((wn & 1) << 5) + (tig << 1);

    // d-dependent index parts (separable; verified against attention staging)
    int dpart[4][2];
#pragma unroll
    for (int ni = 0; ni < 4; ni++)
#pragma unroll
        for (int el = 0; el < 2; el++) {
            int d = dbase + (ni << 3) + el;
            int dq = d >> 2, e = d & 3;
            if (sec == 0)
                dpart[ni][el] = ((dq >> 1) << 7) + ((dq & 1) << 1) + (e << 2);
            else if (sec == 1)
                dpart[ni][el] = ((dq >> 1) << 9) + (dq & 1) + (e << 2);
            else
                dpart[ni][el] = ((dq >> 2) << 7) + (((dq >> 1) & 1) << 1)
                              + ((dq & 1) << 6) + (e << 4);
        }

#pragma unroll
    for (int mi = 0; mi < 4; mi++)
#pragma unroll
        for (int h = 0; h < 2; h++) {
            int token = m0 + (wm << 6) + (mi << 4) + gid + (h << 3);
            int cx = coords[4 * token + 1];
            int cy = coords[4 * token + 2];
            int cz = coords[4 * token + 3];
            int w = ((cx >> 3) << 4) + ((cy >> 3) << 2) + (cz >> 3);
            int m = ((cz & 7) << 6) + ((cy & 7) << 3) + (cx & 7);
            int wh_ = (w << 3) + head;

            if (sec == 0) {
                float* bp = g_q + ((size_t)((wh_ << 1) + (m >> 8)) << 14);
                int r = m & 255;
                int kp = ((r >> 4) << 10) + ((r & 7) << 4) + ((r >> 3) & 1);
#pragma unroll
                for (int ni = 0; ni < 4; ni++)
#pragma unroll
                    for (int el = 0; el < 2; el++)
                        bp[kp + dpart[ni][el]] = __uint_as_float(
                            cvt_tf32(c[mi][ni][2 * h + el] * 0.125f));
            } else if (sec == 1) {
                float* bp = g_k + ((size_t)((wh_ << 3) + (m >> 6)) << 12);
                int key = m & 63;
                int kp = ((key >> 4) << 7) + ((key & 7) << 4)
                       + (((key >> 3) & 1) << 1);
#pragma unroll
                for (int ni = 0; ni < 4; ni++)
#pragma unroll
                    for (int el = 0; el < 2; el++)
                        bp[kp + dpart[ni][el]] = __uint_as_float(
                            cvt_tf32(c[mi][ni][2 * h + el]));
            } else {
                float* bp = g_v + ((size_t)((wh_ << 3) + (m >> 6)) << 12);
                int key = m & 63;
                int kp = ((key >> 3) << 9) + ((key >> 2) & 1) + ((key & 3) << 2);
#pragma unroll
                for (int ni = 0; ni < 4; ni++)
#pragma unroll
                    for (int el = 0; el < 2; el++)
                        bp[kp + dpart[ni][el]] = __uint_as_float(
                            cvt_tf32(c[mi][ni][2 * h + el]));
            }
        }
}

// ---------------------------------------------------------------------------
// K2: window attention — staging is now a straight image copy (no cvt,
// no swizzle math).  Mainloop/softmax/PV unchanged from R8.
// ---------------------------------------------------------------------------
#define ATTN_SMEM_BYTES ((8192 * 2 + 3 * 4096 + 3 * 4096) * 4)

__global__ __launch_bounds__(256, 1)
void window_attn_mma()
{
    extern __shared__ float sm[];
    float* sQ = sm;              // 16384 floats
    float* sK = sm + 16384;      // 3 x 4096 floats
    float* sV = sm + 16384 + 3 * 4096;   // 3 x 4096 floats

    const int tid = threadIdx.x;
    const int lane = tid & 31, wid = tid >> 5;
    const int gid = lane >> 2, tig = lane & 3;
    const int qt = blockIdx.x;          // 0..1
    const int wh = blockIdx.y;          // w*8 + h
    const int m0 = qt << 8;             // 256 rows per CTA

    const float* qimg = g_q + ((size_t)((wh << 1) + qt) << 14);
    const float* kimg = g_k + ((size_t)(wh << 3) << 12);
    const float* vimg = g_v + ((size_t)(wh << 3) << 12);

    auto stage = [&](int c, int bi) {
        float* sKc = sK + bi * 4096;
        float* sVc = sV + bi * 4096;
        const float* ks = kimg + ((size_t)c << 12);
        const float* vs = vimg + ((size_t)c << 12);
#pragma unroll
        for (int p = 0; p < 4; p++) {
            int i4 = (p << 8) + tid;
            *(float4*)&sKc[i4 << 2] = *(const float4*)&ks[i4 << 2];
            *(float4*)&sVc[i4 << 2] = *(const float4*)&vs[i4 << 2];
        }
    };

    // ---- stage Q once: straight copy ----
#pragma unroll
    for (int p = 0; p < 16; p++) {
        int i4 = (p << 8) + tid;
        *(float4*)&sQ[i4 << 2] = *(const float4*)&qimg[i4 << 2];
    }
    stage(0, 0);

    float cO[2][8][4];
#pragma unroll
    for (int mi = 0; mi < 2; mi++)
#pragma unroll
        for (int f = 0; f < 8; f++)
#pragma unroll
            for (int q = 0; q < 4; q++) cO[mi][f][q] = 0.f;
    float mr[2][2], lr[2][2];
#pragma unroll
    for (int mi = 0; mi < 2; mi++) {
        mr[mi][0] = -1e30f; mr[mi][1] = -1e30f;
        lr[mi][0] = 0.f;    lr[mi][1] = 0.f;
    }

    int bufc = 0;
    for (int c = 0; c < 8; c++) {
        if (c < 7) {
            int bn = bufc + 1; if (bn == 3) bn = 0;
            stage(c + 1, bn);
        }
        __syncthreads();
        const float* sKc = sK + bufc * 4096;
        const float* sVc = sV + bufc * 4096;

        float cS[2][8][4];
#pragma unroll
        for (int mi = 0; mi < 2; mi++)
#pragma unroll
            for (int f = 0; f < 8; f++)
#pragma unroll
                for (int q = 0; q < 4; q++) cS[mi][f][q] = 0.f;
#pragma unroll
        for (int tkd = 0; tkd < 8; tkd++) {
            uint4 qa[2];
#pragma unroll
            for (int mi = 0; mi < 2; mi++)
                qa[mi] = *(const uint4*)&sQ[(((((wid << 1) + mi) << 3) + tkd) << 7)
                                            + (lane << 2)];
#pragma unroll
            for (int tn2 = 0; tn2 < 4; tn2++) {
                uint4 kb = *(const uint4*)&sKc[(((tkd << 2) + tn2) << 7) + (lane << 2)];
#pragma unroll
                for (int mi = 0; mi < 2; mi++) {
                    mma_tf32(cS[mi][tn2 * 2],     qa[mi].x, qa[mi].y, qa[mi].z,
                             qa[mi].w, kb.x, kb.y);
                    mma_tf32(cS[mi][tn2 * 2 + 1], qa[mi].x, qa[mi].y, qa[mi].z,
                             qa[mi].w, kb.z, kb.w);
                }
            }
        }

#pragma unroll
        for (int mi = 0; mi < 2; mi++) {
            float smax0 = -1e30f, smax1 = -1e30f;
#pragma unroll
            for (int f = 0; f < 8; f++) {
                smax0 = fmaxf(smax0, fmaxf(cS[mi][f][0], cS[mi][f][1]));
                smax1 = fmaxf(smax1, fmaxf(cS[mi][f][2], cS[mi][f][3]));
            }
            smax0 = fmaxf(smax0, __shfl_xor_sync(0xffffffffu, smax0, 1));
            smax0 = fmaxf(smax0, __shfl_xor_sync(0xffffffffu, smax0, 2));
            smax1 = fmaxf(smax1, __shfl_xor_sync(0xffffffffu, smax1, 1));
            smax1 = fmaxf(smax1, __shfl_xor_sync(0xffffffffu, smax1, 2));
            float mn0 = fmaxf(mr[mi][0], smax0), mn1 = fmaxf(mr[mi][1], smax1);
            float corr0 = __expf(mr[mi][0] - mn0), corr1 = __expf(mr[mi][1] - mn1);
            mr[mi][0] = mn0; mr[mi][1] = mn1;
            float rs0 = 0.f, rs1 = 0.f;
#pragma unroll
            for (int f = 0; f < 8; f++) {
                float p0 = __expf(cS[mi][f][0] - mn0);
                float p1 = __expf(cS[mi][f][1] - mn0);
                float p2 = __expf(cS[mi][f][2] - mn1);
                float p3 = __expf(cS[mi][f][3] - mn1);
                rs0 += p0 + p1; rs1 += p2 + p3;
                cS[mi][f][0] = __uint_as_float(cvt_tf32(p0));
                cS[mi][f][1] = __uint_as_float(cvt_tf32(p1));
                cS[mi][f][2] = __uint_as_float(cvt_tf32(p2));
                cS[mi][f][3] = __uint_as_float(cvt_tf32(p3));
            }
            rs0 += __shfl_xor_sync(0xffffffffu, rs0, 1);
            rs0 += __shfl_xor_sync(0xffffffffu, rs0, 2);
            rs1 += __shfl_xor_sync(0xffffffffu, rs1, 1);
            rs1 += __shfl_xor_sync(0xffffffffu, rs1, 2);
            lr[mi][0] = lr[mi][0] * corr0 + rs0;
            lr[mi][1] = lr[mi][1] * corr1 + rs1;
#pragma unroll
            for (int f = 0; f < 8; f++) {
                cO[mi][f][0] *= corr0; cO[mi][f][1] *= corr0;
                cO[mi][f][2] *= corr1; cO[mi][f][3] *= corr1;
            }
        }

        const int src  = (lane & 28) | (tig >> 1);
        const int src2 = src + 2;
        const bool odd = tig & 1;
#pragma unroll
        for (int kb = 0; kb < 8; kb++) {
            uint32_t pa[2][4];
#pragma unroll
            for (int mi = 0; mi < 2; mi++) {
                float v0 = __shfl_sync(0xffffffffu, cS[mi][kb][0], src);
                float v1 = __shfl_sync(0xffffffffu, cS[mi][kb][1], src);
                float v2 = __shfl_sync(0xffffffffu, cS[mi][kb][2], src);
                float v3 = __shfl_sync(0xffffffffu, cS[mi][kb][3], src);
                float w0 = __shfl_sync(0xffffffffu, cS[mi][kb][0], src2);
                float w1 = __shfl_sync(0xffffffffu, cS[mi][kb][1], src2);
                float w2 = __shfl_sync(0xffffffffu, cS[mi][kb][2], src2);
                float w3 = __shfl_sync(0xffffffffu, cS[mi][kb][3], src2);
                pa[mi][0] = __float_as_uint(odd ? v1 : v0);
                pa[mi][1] = __float_as_uint(odd ? v3 : v2);
                pa[mi][2] = __float_as_uint(odd ? w1 : w0);
                pa[mi][3] = __float_as_uint(odd ? w3 : w2);
            }
#pragma unroll
            for (int tn = 0; tn < 4; tn++) {
                uint4 vb = *(const uint4*)&sVc[(((kb << 2) + tn) << 7) + (lane << 2)];
#pragma unroll
                for (int mi = 0; mi < 2; mi++) {
                    mma_tf32(cO[mi][tn * 2],     pa[mi][0], pa[mi][1], pa[mi][2],
                             pa[mi][3], vb.x, vb.y);
                    mma_tf32(cO[mi][tn * 2 + 1], pa[mi][0], pa[mi][1], pa[mi][2],
                             pa[mi][3], vb.z, vb.w);
                }
            }
        }
        bufc++; if (bufc == 3) bufc = 0;
    }

    // ---- epilogue: 1/l and inverse-permutation scatter (unchanged) ----
    const int w = wh >> 3, h = wh & 7;
    const int wx = w >> 4, wy = (w >> 2) & 3, wz = w & 3;
#pragma unroll
    for (int mi = 0; mi < 2; mi++)
#pragma unroll
        for (int rr = 0; rr < 2; rr++) {
            int m = m0 + (wid << 5) + (mi << 4) + gid + (rr << 3);
            int mz = m >> 6, my = (m >> 3) & 7, mx = m & 7;
            int n = (wz * 8 + mz) * 1024 + (wy * 8 + my) * 32 + (wx * 8 + mx);
            float inv = 1.0f / lr[mi][rr];
            float* dsth = g_h + (size_t)n * 512 + h * 64 + (tig << 1);
#pragma unroll
            for (int f = 0; f < 8; f++)
                *(float2*)&dsth[f << 3] =
                    make_float2(cO[mi][f][2 * rr] * inv,
                                cO[mi][f][2 * rr + 1] * inv);
        }
}

// ---------------------------------------------------------------------------
// kernel_launch
// inputs: x_feats, coords, w_qkv, b_qkv, gamma_q, gamma_k, w_out, b_out
// ---------------------------------------------------------------------------
extern "C" void kernel_launch(void* const* d_in, const int* in_sizes, int n_in,
                              void* d_out, int out_size)
{
    (void)in_sizes; (void)n_in; (void)out_size;
    const float* x      = (const float*)d_in[0];
    const int*   coords = (const int*)  d_in[1];
    const float* wqkv   = (const float*)d_in[2];
    const float* bqkv   = (const float*)d_in[3];
    const float* gq     = (const float*)d_in[4];
    const float* gk     = (const float*)d_in[5];
    const float* wout   = (const float*)d_in[6];
    const float* bout   = (const float*)d_in[7];
    float* outp = (float*)d_out;

    cudaFuncSetAttribute(window_attn_mma,
                         cudaFuncAttributeMaxDynamicSharedMemorySize,
                         ATTN_SMEM_BYTES);

    float* wqkvP;  cudaGetSymbolAddress((void**)&wqkvP, g_wqkvP);
    float* woutP;  cudaGetSymbolAddress((void**)&woutP, g_woutP);
    float* hbuf;   cudaGetSymbolAddress((void**)&hbuf,  g_h);

    prepack_b<<<dim3(12, 16, 2), 256>>>(wqkv, wqkvP, wout, woutP);
    gemm_mma<<<dim3(12, 256), 256>>>(x, wqkvP, bqkv, coords, gq, gk, nullptr, 0);
    window_attn_mma<<<dim3(2, 512), 256, ATTN_SMEM_BYTES>>>();
    gemm_mma<<<dim3(4, 256), 256>>>(hbuf, woutP, bout, nullptr, nullptr, nullptr,
                                    outp, 1);
}